// round 14
// baseline (speedup 1.0000x reference)
#include <cuda_runtime.h>
#include <cuda_bf16.h>

// relu(segment_sum(x @ W^T + b))  ==  relu(segment_sum(x) @ W^T + count * b)
// N=500000, H=256, B=1024, seg_ids sorted ascending.
//
// KEY CHANGE vs R13: the epilogue GEMM is FUSED INTO SEGSUM'S FLUSH PATH.
// segsum is 85% DRAM-bound with issue=11% / fma=6% -- the GEMM's 140 MFLOP
// rides for free in those idle issue slots. Every standalone epilogue
// variant (R3-R13) floored at 18-27us; this removes it from the timeline.
//
//  1. segsum_fused: hot loop UNTOUCHED (77us, roofline). Blocks 0..63 write
//     W4T[k4][j] (k-major W) at start, then bump a 64-arrival flag. A flush
//     now computes y[j] = acc . W[j] (block matvec: broadcast LDS of acc +
//     coalesced LDG of W4T) and atomicAdds into preact[g][j]. Flushes are
//     rare (~2/block) and spin on the flag first (writers never wait on
//     readers -> no deadlock; flag is monotonic across graph replays and
//     W4T rewrites are value-identical, so the race is benign).
//  2. relu_kernel: out = relu(preact + count*b); self-zeros preact/count
//     for the next replay (each block exclusively owns its rows).

#define H 256
#define HV 64                  // H/4
#define B 1024
#define TARGET_GRID 1184
#define RPI 32                 // segsum rows per iteration

__device__ float g_preact[B * H];     // [g][j] pre-activation (zero-init,
                                      //        re-zeroed by relu_kernel)
__device__ float g_count[B];          // nodes per segment (zero-init,
                                      //        re-zeroed by relu_kernel)
__device__ float g_W4T[H * H];        // [k4][j] float4-chunk k-major W
__device__ unsigned int g_w4t_ready;  // monotonic arrival flag

// ---------------------------------------------------------------------------
// Fused flush: y[j] = (block-partial segment sum) . W[j], atomicAdd preact.
// Block-uniform control flow (seg values identical across threads), so the
// internal __syncthreads are safe.
// ---------------------------------------------------------------------------
__device__ __forceinline__ void flush_full(
    float4& acc, int cur, int c, int rowoff, int tid,
    float4 (*sacc)[HV], float4* facc)
{
    sacc[rowoff][c] = acc;
    acc = make_float4(0.f, 0.f, 0.f, 0.f);

    // wait until all 64 W4T writer blocks have finished (instant after ~5us)
    if (tid == 0) {
        volatile unsigned int* f = &g_w4t_ready;
        while (*f < 64u) {}
    }
    __syncthreads();                    // sacc visible + flag observed

    if (tid < HV) {                     // reduce the 4 rowoff partials
        float4 a0 = sacc[0][tid], a1 = sacc[1][tid];
        float4 a2 = sacc[2][tid], a3 = sacc[3][tid];
        facc[tid] = make_float4((a0.x + a1.x) + (a2.x + a3.x),
                                (a0.y + a1.y) + (a2.y + a3.y),
                                (a0.z + a1.z) + (a2.z + a3.z),
                                (a0.w + a1.w) + (a2.w + a3.w));
    }
    __syncthreads();                    // facc ready

    // matvec: thread j = tid. Per k4: 1 broadcast LDS + 1 coalesced LDG.128
    // (W4T is L2-resident: 256KB, reused by every flush chip-wide) + 4 FFMA.
    const float4* __restrict__ w4t = reinterpret_cast<const float4*>(g_W4T);
    float y = 0.f;
    #pragma unroll 4
    for (int k4 = 0; k4 < HV; ++k4) {
        float4 w = __ldg(&w4t[k4 * 256 + tid]);
        float4 a = facc[k4];
        y += w.x * a.x + w.y * a.y + w.z * a.z + w.w * a.w;
    }
    atomicAdd(&g_preact[cur * H + tid], y);
    // no trailing sync needed: the next flush's first __syncthreads (after
    // its sacc store, which touches no state read here) provides ordering
    // before facc is rewritten.
}

// ---------------------------------------------------------------------------
// Kernel 1: segment-sum of x with fused per-flush GEMM. Hot loop identical
// to the proven 77us / 85%-DRAM version.
// ---------------------------------------------------------------------------
__global__ void __launch_bounds__(H) segsum_kernel(
    const float* __restrict__ x, const int* __restrict__ seg,
    const float* __restrict__ W, int N, int rows_per_block)
{
    __shared__ __align__(16) float4 sacc[4][HV];   // 4KB  flush gather
    __shared__ __align__(16) float4 facc[HV];      // 1KB  reduced acc

    // preamble: blocks 0..63 write W4T[k4=blockIdx][j=tid] then arrive
    if (blockIdx.x < 64) {
        reinterpret_cast<float4*>(g_W4T)[blockIdx.x * 256 + threadIdx.x] =
            __ldg(&reinterpret_cast<const float4*>(W)[threadIdx.x * HV + blockIdx.x]);
        __threadfence();
        __syncthreads();
        if (threadIdx.x == 0) atomicAdd(&g_w4t_ready, 1u);
    }

    int r0 = blockIdx.x * rows_per_block;
    int r1 = min(r0 + rows_per_block, N);
    if (r0 >= r1) return;

    const int tid    = threadIdx.x;
    const int c      = tid & 63;
    const int rowoff = tid >> 6;
    const float4* __restrict__ x4 = reinterpret_cast<const float4*>(x);

    float4 acc = make_float4(0.f, 0.f, 0.f, 0.f);
    int cur       = __ldg(&seg[r0]);
    int run_start = r0;

    int r = r0;
    for (; r + RPI <= r1; r += RPI) {
        size_t base = (size_t)(r + rowoff) * HV + c;
        float4 v0 = __ldg(&x4[base + 0 * 4 * HV]);
        float4 v1 = __ldg(&x4[base + 1 * 4 * HV]);
        float4 v2 = __ldg(&x4[base + 2 * 4 * HV]);
        float4 v3 = __ldg(&x4[base + 3 * 4 * HV]);
        float4 v4 = __ldg(&x4[base + 4 * 4 * HV]);
        float4 v5 = __ldg(&x4[base + 5 * 4 * HV]);
        float4 v6 = __ldg(&x4[base + 6 * 4 * HV]);
        float4 v7 = __ldg(&x4[base + 7 * 4 * HV]);
        int s_last = __ldg(&seg[r + RPI - 1]);

        if (s_last == cur) {
            acc.x += ((v0.x + v1.x) + (v2.x + v3.x)) + ((v4.x + v5.x) + (v6.x + v7.x));
            acc.y += ((v0.y + v1.y) + (v2.y + v3.y)) + ((v4.y + v5.y) + (v6.y + v7.y));
            acc.z += ((v0.z + v1.z) + (v2.z + v3.z)) + ((v4.z + v5.z) + (v6.z + v7.z));
            acc.w += ((v0.w + v1.w) + (v2.w + v3.w)) + ((v4.w + v5.w) + (v6.w + v7.w));
        } else {
            // segment boundary inside this group (block-uniform path)
            float4 vv[8] = {v0, v1, v2, v3, v4, v5, v6, v7};
            #pragma unroll
            for (int k = 0; k < RPI; ++k) {
                int rr = r + k;
                int s = __ldg(&seg[rr]);
                if (s != cur) {
                    flush_full(acc, cur, c, rowoff, tid, sacc, facc);
                    if (tid == 0)
                        atomicAdd(&g_count[cur], (float)(rr - run_start));
                    cur = s; run_start = rr;
                }
                if ((k & 3) == rowoff) {
                    float4 v = vv[k >> 2];
                    acc.x += v.x; acc.y += v.y; acc.z += v.z; acc.w += v.w;
                }
            }
        }
    }
    for (; r < r1; ++r) {
        int s = __ldg(&seg[r]);
        if (s != cur) {
            flush_full(acc, cur, c, rowoff, tid, sacc, facc);
            if (tid == 0) atomicAdd(&g_count[cur], (float)(r - run_start));
            cur = s; run_start = r;
        }
        if (rowoff == 0) {
            float4 v = __ldg(&x4[(size_t)r * HV + c]);
            acc.x += v.x; acc.y += v.y; acc.z += v.z; acc.w += v.w;
        }
    }
    flush_full(acc, cur, c, rowoff, tid, sacc, facc);
    if (tid == 0) atomicAdd(&g_count[cur], (float)(r1 - run_start));
}

// ---------------------------------------------------------------------------
// Kernel 2: out = relu(preact + count*b); self-zero scratch for next replay.
// 256 blocks x 256 threads, one float4 each. A segment's 64 float4 span 64
// consecutive threads of ONE block, so the count[g] zeroing after the sync
// cannot race with its readers.
// ---------------------------------------------------------------------------
__global__ void __launch_bounds__(256) relu_kernel(
    const float* __restrict__ bias, float* __restrict__ out)
{
    const int idx = blockIdx.x * 256 + threadIdx.x;   // 0..65535
    const int g   = idx >> 6;
    const int c4  = idx & 63;

    float4 p  = reinterpret_cast<const float4*>(g_preact)[idx];
    float cnt = g_count[g];
    float4 b4 = __ldg(&reinterpret_cast<const float4*>(bias)[c4]);

    float4 o;
    o.x = fmaxf(p.x + cnt * b4.x, 0.f);
    o.y = fmaxf(p.y + cnt * b4.y, 0.f);
    o.z = fmaxf(p.z + cnt * b4.z, 0.f);
    o.w = fmaxf(p.w + cnt * b4.w, 0.f);
    reinterpret_cast<float4*>(out)[idx] = o;

    reinterpret_cast<float4*>(g_preact)[idx] = make_float4(0.f, 0.f, 0.f, 0.f);
    __syncthreads();
    if (c4 == 0) g_count[g] = 0.f;
}

// ---------------------------------------------------------------------------
// Launch
// ---------------------------------------------------------------------------
extern "C" void kernel_launch(void* const* d_in, const int* in_sizes, int n_in,
                              void* d_out, int out_size)
{
    const float* x   = (const float*)d_in[0];   // [N, 256]
    const int*   seg = (const int*)  d_in[1];   // [N]
    const float* W   = (const float*)d_in[2];   // [256, 256]
    const float* b   = (const float*)d_in[3];   // [256]
    float* out = (float*)d_out;                 // [1024, 256]

    const int N = in_sizes[0] / H;

    int rpb = (N + TARGET_GRID - 1) / TARGET_GRID;
    rpb = ((rpb + RPI - 1) / RPI) * RPI;        // N=500000 -> 448
    int grid = (N + rpb - 1) / rpb;             // -> 1117

    segsum_kernel<<<grid, H>>>(x, seg, W, N, rpb);
    relu_kernel<<<(B * H / 4) / 256, 256>>>(b, out);
}